// round 5
// baseline (speedup 1.0000x reference)
#include <cuda_runtime.h>
#include <cuda_bf16.h>
#include <math.h>
#include <stdint.h>

#define Bz 4
#define Tz 1024
#define Cz 768
#define Hz 12
#define HDz 64
#define Lz 6
#define Vz 32000
#define BT (Bz*Tz)

// ---------------- scratch (static device globals; no allocations) ----------
__device__ float g_x[BT*Cz];                     // residual stream (fp32)
__device__ __nv_bfloat16 g_lnh[BT*Cz], g_lnl[BT*Cz];     // layernorm out hi/lo
__device__ float g_qkv[BT*3*Cz];                 // qkv (fp32, attention input)
__device__ __nv_bfloat16 g_yh[BT*Cz], g_yl[BT*Cz];       // attention out hi/lo
__device__ __nv_bfloat16 g_hh[BT*4*Cz], g_hl[BT*4*Cz];   // MLP hidden hi/lo
// transposed bf16 hi/lo weights: Wt[N,K] row-major (K contiguous)
__device__ __nv_bfloat16 g_wqkv_h[Lz*3*Cz*Cz], g_wqkv_l[Lz*3*Cz*Cz];
__device__ __nv_bfloat16 g_wproj_h[Lz*Cz*Cz],  g_wproj_l[Lz*Cz*Cz];
__device__ __nv_bfloat16 g_wfc_h[Lz*4*Cz*Cz],  g_wfc_l[Lz*4*Cz*Cz];
__device__ __nv_bfloat16 g_wmlp_h[Lz*Cz*4*Cz], g_wmlp_l[Lz*Cz*4*Cz];
__device__ __nv_bfloat16 g_whead_h[Vz*Cz],     g_whead_l[Vz*Cz];

// ---------------- helpers ---------------------------------------------------
__device__ __forceinline__ uint32_t smem_u32(const void* p) {
    uint32_t a;
    asm("{ .reg .u64 t; cvta.to.shared.u64 t, %1; cvt.u32.u64 %0, t; }"
        : "=r"(a) : "l"(p));
    return a;
}
__device__ __forceinline__ void cpasync16(uint32_t s, const void* g) {
    asm volatile("cp.async.cg.shared.global [%0], [%1], 16;\n" :: "r"(s), "l"(g));
}
#define CP_COMMIT() asm volatile("cp.async.commit_group;\n" ::: "memory")

__device__ __forceinline__ void ldm_x4(uint32_t* r, uint32_t addr) {
    asm volatile("ldmatrix.sync.aligned.m8n8.x4.shared.b16 {%0,%1,%2,%3}, [%4];"
        : "=r"(r[0]), "=r"(r[1]), "=r"(r[2]), "=r"(r[3]) : "r"(addr));
}
__device__ __forceinline__ void mma16816(float* d, const uint32_t* a,
                                         uint32_t b0, uint32_t b1) {
    asm volatile("mma.sync.aligned.m16n8k16.row.col.f32.bf16.bf16.f32 "
        "{%0,%1,%2,%3}, {%4,%5,%6,%7}, {%8,%9}, {%0,%1,%2,%3};"
        : "+f"(d[0]), "+f"(d[1]), "+f"(d[2]), "+f"(d[3])
        : "r"(a[0]), "r"(a[1]), "r"(a[2]), "r"(a[3]), "r"(b0), "r"(b1));
}

__device__ __forceinline__ void split_bf16(float v, __nv_bfloat16& hi, __nv_bfloat16& lo) {
    hi = __float2bfloat16(v);
    lo = __float2bfloat16(v - __bfloat162float(hi));
}
__device__ __forceinline__ float gelu_exact(float v) {
    return 0.5f * v * (1.0f + erff(v * 0.70710678118654752f));
}

// ---------------- embedding ------------------------------------------------
__global__ void k_embed(const int* __restrict__ idx,
                        const float* __restrict__ wte,
                        const float* __restrict__ wpe) {
    int i = blockIdx.x * blockDim.x + threadIdx.x;
    if (i >= BT*Cz) return;
    int c  = i % Cz;
    int bt = i / Cz;
    int t  = bt % Tz;
    int tok = idx[bt];
    g_x[i] = wte[(size_t)tok * Cz + c] + wpe[(size_t)t * Cz + c];
}

// ---------------- weight transpose + bf16 hi/lo split ----------------------
__global__ void k_wprep(const float* __restrict__ W,
                        __nv_bfloat16* __restrict__ Whi,
                        __nv_bfloat16* __restrict__ Wlo, int K, int N) {
    __shared__ float t[32][33];
    int n0 = blockIdx.x * 32, k0 = blockIdx.y * 32;
    int tx = threadIdx.x, ty = threadIdx.y;   // 32 x 8
    #pragma unroll
    for (int j = 0; j < 32; j += 8)
        t[ty + j][tx] = W[(size_t)(k0 + ty + j) * N + n0 + tx];
    __syncthreads();
    #pragma unroll
    for (int j = 0; j < 32; j += 8) {
        float v = t[tx][ty + j];
        __nv_bfloat16 hi, lo; split_bf16(v, hi, lo);
        size_t o = (size_t)(n0 + ty + j) * K + k0 + tx;
        Whi[o] = hi; Wlo[o] = lo;
    }
}

// ---------------- layernorm -> bf16 hi/lo ----------------------------------
__global__ void k_ln(const float* __restrict__ x,
                     const float* __restrict__ w,
                     const float* __restrict__ b,
                     __nv_bfloat16* __restrict__ ohi,
                     __nv_bfloat16* __restrict__ olo) {
    int row = blockIdx.x;
    int tid = threadIdx.x;
    const float* xr = x + (size_t)row * Cz;
    float v0 = xr[tid], v1 = xr[tid + 256], v2 = xr[tid + 512];

    __shared__ float red[256];
    red[tid] = v0 + v1 + v2;
    __syncthreads();
    #pragma unroll
    for (int off = 128; off > 0; off >>= 1) {
        if (tid < off) red[tid] += red[tid + off];
        __syncthreads();
    }
    float mean = red[0] * (1.0f / Cz);
    __syncthreads();
    float d0 = v0 - mean, d1 = v1 - mean, d2 = v2 - mean;
    red[tid] = d0*d0 + d1*d1 + d2*d2;
    __syncthreads();
    #pragma unroll
    for (int off = 128; off > 0; off >>= 1) {
        if (tid < off) red[tid] += red[tid + off];
        __syncthreads();
    }
    float rstd = rsqrtf(red[0] * (1.0f / Cz) + 1e-5f);

    size_t base = (size_t)row * Cz;
    float r0 = d0 * rstd * w[tid]       + b[tid];
    float r1 = d1 * rstd * w[tid + 256] + b[tid + 256];
    float r2 = d2 * rstd * w[tid + 512] + b[tid + 512];
    __nv_bfloat16 hi, lo;
    split_bf16(r0, hi, lo); ohi[base + tid]       = hi; olo[base + tid]       = lo;
    split_bf16(r1, hi, lo); ohi[base + tid + 256] = hi; olo[base + tid + 256] = lo;
    split_bf16(r2, hi, lo); ohi[base + tid + 512] = hi; olo[base + tid + 512] = lo;
}

// ---------------- mma.sync GEMM: block (MT*32)x256, warp 64x(MT*16) --------
// out[M,N] = (Ahi+Alo)[M,K] @ (Bhi+Blo)[N,K]^T   (3-product bf16 split)
// mode: 0 = +bias->fp32 | 1 = +bias+res->fp32 | 2 = gelu(+bias)->bf16 hi/lo
//       3 = plain->fp32.   8 warps as 2(M) x 4(N); warp tile (MT*16) x 64.
#define MMR 144                        // row stride bytes (128 data + 16 pad)

template<int MT>
__device__ __forceinline__ void mm_load(
    uint32_t so, int chunk, int tid,
    const __nv_bfloat16* Ahi, const __nv_bfloat16* Alo,
    const __nv_bfloat16* Bhi, const __nv_bfloat16* Blo,
    int gm0, int gn0, int K) {
    constexpr int BM = MT * 32;
    constexpr int ABYTES = BM * MMR;
    constexpr int BBYTES = 256 * MMR;
    int k0 = chunk * 64;
    constexpr int TOT = (2 * BM + 512) * 8;
    #pragma unroll
    for (int i = tid; i < TOT; i += 256) {
        int r = i >> 3, seg = i & 7;
        const __nv_bfloat16* src;
        uint32_t dst;
        if (r < BM) {
            src = Ahi + (size_t)(gm0 + r) * K;
            dst = so + r * MMR;
        } else if (r < 2 * BM) {
            int rr = r - BM;
            src = Alo + (size_t)(gm0 + rr) * K;
            dst = so + ABYTES + rr * MMR;
        } else if (r < 2 * BM + 256) {
            int rr = r - 2 * BM;
            src = Bhi + (size_t)(gn0 + rr) * K;
            dst = so + 2 * ABYTES + rr * MMR;
        } else {
            int rr = r - 2 * BM - 256;
            src = Blo + (size_t)(gn0 + rr) * K;
            dst = so + 2 * ABYTES + BBYTES + rr * MMR;
        }
        cpasync16(dst + seg * 16, src + k0 + seg * 8);
    }
    CP_COMMIT();
}

template<int MT>
__global__ void __launch_bounds__(256, 1) k_mgemm(
    const __nv_bfloat16* __restrict__ Ahi, const __nv_bfloat16* __restrict__ Alo,
    const __nv_bfloat16* __restrict__ Bhi, const __nv_bfloat16* __restrict__ Blo,
    const float* __restrict__ bias, const float* res,
    float* outf, __nv_bfloat16* outhi, __nv_bfloat16* outlo,
    int M, int N, int K, int mode) {
    constexpr int BM = MT * 32;
    constexpr int ABYTES = BM * MMR;
    constexpr int BBYTES = 256 * MMR;
    constexpr int STAGE = 2 * ABYTES + 2 * BBYTES;
    extern __shared__ char smem[];
    uint32_t sbase = smem_u32(smem);
    int tid = threadIdx.x, lane = tid & 31, warp = tid >> 5;
    int wm = (warp >> 2) * (MT * 16);    // warp M offset (2 warp-rows)
    int wn = (warp & 3) * 64;            // warp N offset (4 warp-cols)
    int gn0 = blockIdx.x * 256, gm0 = blockIdx.y * BM;
    int nch = K >> 6;

    float acc[MT][8][4];
    #pragma unroll
    for (int i = 0; i < MT; i++)
        #pragma unroll
        for (int j = 0; j < 8; j++)
            #pragma unroll
            for (int e = 0; e < 4; e++) acc[i][j][e] = 0.f;

    mm_load<MT>(sbase,         0, tid, Ahi, Alo, Bhi, Blo, gm0, gn0, K);
    mm_load<MT>(sbase + STAGE, 1, tid, Ahi, Alo, Bhi, Blo, gm0, gn0, K);

    int lrow = lane & 15;
    int lkb  = (lane >> 4) * 16;         // k-half byte offset

    for (int i = 0; i < nch; i++) {
        if (i + 1 < nch) asm volatile("cp.async.wait_group 1;\n" ::: "memory");
        else             asm volatile("cp.async.wait_group 0;\n" ::: "memory");
        __syncthreads();

        uint32_t so = sbase + (i & 1) * STAGE;
        uint32_t arow = so + (wm + lrow) * MMR;
        uint32_t brow = so + 2 * ABYTES + (wn + lrow) * MMR;

        #pragma unroll
        for (int ks = 0; ks < 4; ks++) {
            uint32_t kb = (uint32_t)(ks * 32) + lkb;
            uint32_t bh[4][4], bl[4][4];
            #pragma unroll
            for (int np = 0; np < 4; np++) {
                ldm_x4(bh[np], brow + np * (16 * MMR) + kb);
                ldm_x4(bl[np], brow + BBYTES + np * (16 * MMR) + kb);
            }
            #pragma unroll
            for (int mt = 0; mt < MT; mt++) {
                uint32_t ah[4], al[4];
                ldm_x4(ah, arow + mt * (16 * MMR) + kb);
                ldm_x4(al, arow + ABYTES + mt * (16 * MMR) + kb);
                #pragma unroll
                for (int nt = 0; nt < 8; nt++) {
                    int np = nt >> 1, h = nt & 1;
                    mma16816(acc[mt][nt], ah, bh[np][h], bh[np][h + 2]);
                    mma16816(acc[mt][nt], al, bh[np][h], bh[np][h + 2]);
                    mma16816(acc[mt][nt], ah, bl[np][h], bl[np][h + 2]);
                }
            }
        }
        __syncthreads();
        if (i + 2 < nch)
            mm_load<MT>(sbase + (i & 1) * STAGE, i + 2, tid,
                        Ahi, Alo, Bhi, Blo, gm0, gn0, K);
    }

    // epilogue
    int r  = lane >> 2;
    int c2 = (lane & 3) * 2;
    #pragma unroll
    for (int mt = 0; mt < MT; mt++) {
        #pragma unroll
        for (int nt = 0; nt < 8; nt++) {
            int m = gm0 + wm + mt * 16 + r;
            int n = gn0 + wn + nt * 8 + c2;
            float* d = acc[mt][nt];
            #pragma unroll
            for (int hh = 0; hh < 2; hh++) {
                int mm = m + hh * 8;
                float v0 = d[2*hh], v1 = d[2*hh + 1];
                if (mode == 2) {
                    v0 = gelu_exact(v0 + bias[n]);
                    v1 = gelu_exact(v1 + bias[n + 1]);
                    __nv_bfloat16 h0, l0, h1, l1;
                    split_bf16(v0, h0, l0); split_bf16(v1, h1, l1);
                    *(__nv_bfloat162*)(outhi + (size_t)mm * N + n) = __nv_bfloat162(h0, h1);
                    *(__nv_bfloat162*)(outlo + (size_t)mm * N + n) = __nv_bfloat162(l0, l1);
                } else {
                    if (mode != 3) { v0 += bias[n]; v1 += bias[n + 1]; }
                    if (mode == 1) {
                        const float2 rv = *(const float2*)(res + (size_t)mm * N + n);
                        v0 += rv.x; v1 += rv.y;
                    }
                    *(float2*)(outf + (size_t)mm * N + n) = make_float2(v0, v1);
                }
            }
        }
    }
}

// ---------------- flash-tiled causal attention -----------------------------
#define ASTR 68                         // floats per smem row (272B, 16B-mult)
#define ASMEM (4 * 64 * ASTR * 4)       // Qs, Ks, Vs, Ps

__global__ void __launch_bounds__(256) k_fattn(
    const float* __restrict__ qkv,
    __nv_bfloat16* __restrict__ yh, __nv_bfloat16* __restrict__ yl) {
    extern __shared__ float sm[];
    float* Qs = sm;
    float* Ks = sm + 64 * ASTR;
    float* Vs = sm + 2 * 64 * ASTR;
    float* Ps = sm + 3 * 64 * ASTR;

    int q0 = blockIdx.x * 64, h = blockIdx.y, b = blockIdx.z;
    int tid = threadIdx.x, lane = tid & 31, warp = tid >> 5;
    int r = lane >> 2, c = lane & 3;
    int qrow = warp * 8 + r;             // local query row
    int qglob = q0 + qrow;

    {
        const float4* g = (const float4*)qkv;
        float4* s4 = (float4*)Qs;
        for (int i = tid; i < 1024; i += 256) {
            int row = i >> 4, sg = i & 15;
            s4[row * 17 + sg] = g[((size_t)(b * Tz + q0 + row) * (3*Cz) + h * 64) / 4 + sg];
        }
    }

    float mrow = -1e30f, lrow = 0.f;
    float oacc[16];
    #pragma unroll
    for (int i = 0; i < 16; i++) oacc[i] = 0.f;

    int ntiles = (q0 >> 6) + 1;
    for (int t = 0; t < ntiles; t++) {
        __syncthreads();
        {
            const float4* g = (const float4*)qkv;
            float4* k4 = (float4*)Ks;
            float4* v4 = (float4*)Vs;
            for (int i = tid; i < 1024; i += 256) {
                int row = i >> 4, sg = i & 15;
                size_t gb = ((size_t)(b * Tz + t * 64 + row) * (3*Cz) + h * 64) / 4 + sg;
                k4[row * 17 + sg] = g[gb + Cz / 4];
                v4[row * 17 + sg] = g[gb + 2 * Cz / 4];
            }
        }
        __syncthreads();

        float s[16];
        #pragma unroll
        for (int kk = 0; kk < 16; kk++) s[kk] = 0.f;
        const float4* q4 = (const float4*)Qs + qrow * 17;
        const float4* k4b = (const float4*)Ks;
        #pragma unroll 4
        for (int d4 = 0; d4 < 16; d4++) {
            float4 qv = q4[d4];
            #pragma unroll
            for (int kk = 0; kk < 16; kk++) {
                float4 kv = k4b[(kk * 4 + c) * 17 + d4];
                s[kk] += qv.x * kv.x + qv.y * kv.y + qv.z * kv.z + qv.w * kv.w;
            }
        }
        bool maskt = (t == ntiles - 1);
        float tmax = -1e30f;
        #pragma unroll
        for (int kk = 0; kk < 16; kk++) {
            s[kk] *= 0.125f;
            if (maskt && (t * 64 + kk * 4 + c) > qglob) s[kk] = -1e30f;
            tmax = fmaxf(tmax, s[kk]);
        }
        tmax = fmaxf(tmax, __shfl_xor_sync(0xffffffffu, tmax, 1));
        tmax = fmaxf(tmax, __shfl_xor_sync(0xffffffffu, tmax, 2));
        float mnew = fmaxf(mrow, tmax);
        float scale = __expf(mrow - mnew);
        float psum = 0.f;
        #pragma unroll
        for (int kk = 0; kk < 16; kk++) {
            float p = __expf(s[kk] - mnew);
            s[kk] = p;
            psum += p;
            Ps[qrow * ASTR + kk * 4 + c] = p;
        }
        psum += __shfl_xor_sync(0xffffffffu, psum, 1);
        psum += __shfl_xor_sync(0xffffffffu, psum, 2);
        lrow = lrow * scale + psum;
        #pragma unroll
        for (int i = 0; i < 16; i++) oacc[i] *= scale;
        mrow = mnew;
        __syncwarp();

        const float4* p4 = (const float4*)Ps + qrow * 17;
        const float4* v4b = (const float4*)Vs;
        #pragma unroll 2
        for (int kq = 0; kq < 16; kq++) {
            float4 pv = p4[kq];
            #pragma unroll
            for (int j = 0; j < 4; j++) {
                float pj = (j == 0) ? pv.x : (j == 1) ? pv.y : (j == 2) ? pv.z : pv.w;
                const float4* vr = v4b + (kq * 4 + j) * 17 + c * 4;
                #pragma unroll
                for (int e = 0; e < 4; e++) {
                    float4 vv = vr[e];
                    oacc[e*4+0] += pj * vv.x;
                    oacc[e*4+1] += pj * vv.y;
                    oacc[e*4+2] += pj * vv.z;
                    oacc[e*4+3] += pj * vv.w;
                }
            }
        }
    }

    float inv = 1.0f / lrow;
    size_t base = (size_t)(b * Tz + qglob) * Cz + h * 64 + c * 16;
    #pragma unroll
    for (int g = 0; g < 8; g++) {
        float v0 = oacc[2*g] * inv, v1 = oacc[2*g+1] * inv;
        __nv_bfloat16 h0, l0, h1, l1;
        split_bf16(v0, h0, l0); split_bf16(v1, h1, l1);
        *(__nv_bfloat162*)(yh + base + 2*g) = __nv_bfloat162(h0, h1);
        *(__nv_bfloat162*)(yl + base + 2*g) = __nv_bfloat162(l0, l1);
    }
}

// ---------------- driver ----------------------------------------------------
extern "C" void kernel_launch(void* const* d_in, const int* in_sizes, int n_in,
                              void* d_out, int out_size) {
    const int*   idx    = (const int*)  d_in[0];
    const float* wte    = (const float*)d_in[1];
    const float* wpe    = (const float*)d_in[2];
    const float* ln1_w  = (const float*)d_in[3];
    const float* ln1_b  = (const float*)d_in[4];
    const float* attn_w = (const float*)d_in[5];
    const float* attn_b = (const float*)d_in[6];
    const float* proj_w = (const float*)d_in[7];
    const float* proj_b = (const float*)d_in[8];
    const float* ln2_w  = (const float*)d_in[9];
    const float* ln2_b  = (const float*)d_in[10];
    const float* fc_w   = (const float*)d_in[11];
    const float* fc_b   = (const float*)d_in[12];
    const float* mlp_w  = (const float*)d_in[13];
    const float* mlp_b  = (const float*)d_in[14];
    const float* lnf_w  = (const float*)d_in[15];
    const float* lnf_b  = (const float*)d_in[16];
    const float* head_w = (const float*)d_in[17];
    float* out = (float*)d_out;

    float *px, *pqkv;
    __nv_bfloat16 *plnh, *plnl, *pyh, *pyl, *phh, *phl;
    __nv_bfloat16 *wqh, *wql, *wph, *wpl, *wfh, *wfl, *wmh, *wml, *whh, *whl;
    cudaGetSymbolAddress((void**)&px,   g_x);
    cudaGetSymbolAddress((void**)&pqkv, g_qkv);
    cudaGetSymbolAddress((void**)&plnh, g_lnh);
    cudaGetSymbolAddress((void**)&plnl, g_lnl);
    cudaGetSymbolAddress((void**)&pyh,  g_yh);
    cudaGetSymbolAddress((void**)&pyl,  g_yl);
    cudaGetSymbolAddress((void**)&phh,  g_hh);
    cudaGetSymbolAddress((void**)&phl,  g_hl);
    cudaGetSymbolAddress((void**)&wqh,  g_wqkv_h);
    cudaGetSymbolAddress((void**)&wql,  g_wqkv_l);
    cudaGetSymbolAddress((void**)&wph,  g_wproj_h);
    cudaGetSymbolAddress((void**)&wpl,  g_wproj_l);
    cudaGetSymbolAddress((void**)&wfh,  g_wfc_h);
    cudaGetSymbolAddress((void**)&wfl,  g_wfc_l);
    cudaGetSymbolAddress((void**)&wmh,  g_wmlp_h);
    cudaGetSymbolAddress((void**)&wml,  g_wmlp_l);
    cudaGetSymbolAddress((void**)&whh,  g_whead_h);
    cudaGetSymbolAddress((void**)&whl,  g_whead_l);

    const int SM4 = 2 * (2 * 128 * MMR + 2 * 256 * MMR);   // 221184
    const int SM2 = 2 * (2 * 64 * MMR + 2 * 256 * MMR);    // 184320
    cudaFuncSetAttribute(k_mgemm<4>, cudaFuncAttributeMaxDynamicSharedMemorySize, SM4);
    cudaFuncSetAttribute(k_mgemm<2>, cudaFuncAttributeMaxDynamicSharedMemorySize, SM2);
    cudaFuncSetAttribute(k_fattn,    cudaFuncAttributeMaxDynamicSharedMemorySize, ASMEM);

    dim3 tp(32, 8);
    // ---- my launches 1-3, so that my launch #4 (= global #6, the ncu
    // capture slot given the harness's 2 pre-launches) is the QKV GEMM ----
    k_wprep<<<dim3(3*Cz/32, Cz/32), tp>>>(attn_w, wqh, wql, Cz, 3*Cz);   // 1
    k_embed<<<(BT*Cz + 255) / 256, 256>>>(idx, wte, wpe);                // 2
    k_ln<<<BT, 256>>>(px, ln1_w, ln1_b, plnh, plnl);                     // 3
    // 4: QKV GEMM of layer 0 (ncu capture target)
    k_mgemm<4><<<dim3(3*Cz/256, BT/128), 256, SM4>>>(
        plnh, plnl, wqh, wql, attn_b, nullptr, pqkv, nullptr, nullptr,
        BT, 3*Cz, Cz, 0);

    // remaining weight preps
    k_wprep<<<dim3(Cz/32, Cz/32), tp>>>(proj_w, wph, wpl, Cz, Cz);
    k_wprep<<<dim3(4*Cz/32, Cz/32), tp>>>(fc_w, wfh, wfl, Cz, 4*Cz);
    k_wprep<<<dim3(Cz/32, 4*Cz/32), tp>>>(mlp_w, wmh, wml, 4*Cz, Cz);
    for (int l = 1; l < Lz; l++) {
        k_wprep<<<dim3(3*Cz/32, Cz/32), tp>>>(attn_w + (size_t)l*Cz*3*Cz,
            wqh + (size_t)l*3*Cz*Cz, wql + (size_t)l*3*Cz*Cz, Cz, 3*Cz);
        k_wprep<<<dim3(Cz/32, Cz/32), tp>>>(proj_w + (size_t)l*Cz*Cz,
            wph + (size_t)l*Cz*Cz, wpl + (size_t)l*Cz*Cz, Cz, Cz);
        k_wprep<<<dim3(4*Cz/32, Cz/32), tp>>>(fc_w + (size_t)l*Cz*4*Cz,
            wfh + (size_t)l*4*Cz*Cz, wfl + (size_t)l*4*Cz*Cz, Cz, 4*Cz);
        k_wprep<<<dim3(Cz/32, 4*Cz/32), tp>>>(mlp_w + (size_t)l*4*Cz*Cz,
            wmh + (size_t)l*Cz*4*Cz, wml + (size_t)l*Cz*4*Cz, 4*Cz, Cz);
    }
    k_wprep<<<dim3(Vz/32, Cz/32), tp>>>(head_w, whh, whl, Cz, Vz);

    for (int l = 0; l < Lz; l++) {
        const float* ab = attn_b + (size_t)l * 3 * Cz;
        const float* pb = proj_b + (size_t)l * Cz;
        const float* fb = fc_b   + (size_t)l * 4 * Cz;
        const float* mb = mlp_b  + (size_t)l * Cz;

        if (l > 0) {
            k_ln<<<BT, 256>>>(px, ln1_w + (size_t)l*Cz, ln1_b + (size_t)l*Cz, plnh, plnl);
            k_mgemm<4><<<dim3(3*Cz/256, BT/128), 256, SM4>>>(
                plnh, plnl, wqh + (size_t)l*3*Cz*Cz, wql + (size_t)l*3*Cz*Cz,
                ab, nullptr, pqkv, nullptr, nullptr, BT, 3*Cz, Cz, 0);
        }
        k_fattn<<<dim3(Tz/64, Hz, Bz), 256, ASMEM>>>(pqkv, pyh, pyl);
        // x += y @ Wproj + b       [4096, 768]  (64-row M tiles, 256 N)
        k_mgemm<2><<<dim3(Cz/256, BT/64), 256, SM2>>>(
            pyh, pyl, wph + (size_t)l*Cz*Cz, wpl + (size_t)l*Cz*Cz,
            pb, px, px, nullptr, nullptr, BT, Cz, Cz, 1);
        k_ln<<<BT, 256>>>(px, ln2_w + (size_t)l*Cz, ln2_b + (size_t)l*Cz, plnh, plnl);
        // h = gelu(ln2 @ Wfc + b)  [4096, 3072]
        k_mgemm<4><<<dim3(4*Cz/256, BT/128), 256, SM4>>>(
            plnh, plnl, wfh + (size_t)l*4*Cz*Cz, wfl + (size_t)l*4*Cz*Cz,
            fb, nullptr, nullptr, phh, phl, BT, 4*Cz, Cz, 2);
        // x += h @ Wmlp + b        [4096, 768], K=3072
        k_mgemm<2><<<dim3(Cz/256, BT/64), 256, SM2>>>(
            phh, phl, wmh + (size_t)l*Cz*4*Cz, wml + (size_t)l*Cz*4*Cz,
            mb, px, px, nullptr, nullptr, BT, Cz, 4*Cz, 1);
    }

    k_ln<<<BT, 256>>>(px, lnf_w, lnf_b, plnh, plnl);
    // logits = lnf @ Whead        [4096, 32000]
    k_mgemm<4><<<dim3(Vz/256, BT/128), 256, SM4>>>(
        plnh, plnl, whh, whl, nullptr, nullptr, out, nullptr, nullptr,
        BT, Vz, Cz, 3);
}

// round 7
// speedup vs baseline: 1.0505x; 1.0505x over previous
#include <cuda_runtime.h>
#include <cuda_bf16.h>
#include <math.h>
#include <stdint.h>

#define Bz 4
#define Tz 1024
#define Cz 768
#define Hz 12
#define HDz 64
#define Lz 6
#define Vz 32000
#define BT (Bz*Tz)

// ---------------- scratch (static device globals; no allocations) ----------
__device__ float g_x[BT*Cz];                     // residual stream (fp32)
__device__ __nv_bfloat16 g_lnh[BT*Cz], g_lnl[BT*Cz];     // layernorm out hi/lo
__device__ float g_qkv[BT*3*Cz];                 // qkv (fp32, attention input)
__device__ __nv_bfloat16 g_yh[BT*Cz], g_yl[BT*Cz];       // attention out hi/lo
__device__ __nv_bfloat16 g_hh[BT*4*Cz], g_hl[BT*4*Cz];   // MLP hidden hi/lo
// transposed bf16 hi/lo weights: Wt[N,K] row-major (K contiguous)
__device__ __nv_bfloat16 g_wqkv_h[Lz*3*Cz*Cz], g_wqkv_l[Lz*3*Cz*Cz];
__device__ __nv_bfloat16 g_wproj_h[Lz*Cz*Cz],  g_wproj_l[Lz*Cz*Cz];
__device__ __nv_bfloat16 g_wfc_h[Lz*4*Cz*Cz],  g_wfc_l[Lz*4*Cz*Cz];
__device__ __nv_bfloat16 g_wmlp_h[Lz*Cz*4*Cz], g_wmlp_l[Lz*Cz*4*Cz];
__device__ __nv_bfloat16 g_whead_h[Vz*Cz],     g_whead_l[Vz*Cz];

// ---------------- helpers ---------------------------------------------------
__device__ __forceinline__ uint32_t smem_u32(const void* p) {
    uint32_t a;
    asm("{ .reg .u64 t; cvta.to.shared.u64 t, %1; cvt.u32.u64 %0, t; }"
        : "=r"(a) : "l"(p));
    return a;
}
__device__ __forceinline__ void cpasync16(uint32_t s, const void* g) {
    asm volatile("cp.async.cg.shared.global [%0], [%1], 16;\n" :: "r"(s), "l"(g));
}
#define CP_COMMIT() asm volatile("cp.async.commit_group;\n" ::: "memory")

__device__ __forceinline__ void ldm_x4(uint32_t* r, uint32_t addr) {
    asm volatile("ldmatrix.sync.aligned.m8n8.x4.shared.b16 {%0,%1,%2,%3}, [%4];"
        : "=r"(r[0]), "=r"(r[1]), "=r"(r[2]), "=r"(r[3]) : "r"(addr));
}
__device__ __forceinline__ void mma16816(float* d, const uint32_t* a,
                                         uint32_t b0, uint32_t b1) {
    asm volatile("mma.sync.aligned.m16n8k16.row.col.f32.bf16.bf16.f32 "
        "{%0,%1,%2,%3}, {%4,%5,%6,%7}, {%8,%9}, {%0,%1,%2,%3};"
        : "+f"(d[0]), "+f"(d[1]), "+f"(d[2]), "+f"(d[3])
        : "r"(a[0]), "r"(a[1]), "r"(a[2]), "r"(a[3]), "r"(b0), "r"(b1));
}

__device__ __forceinline__ void split_bf16(float v, __nv_bfloat16& hi, __nv_bfloat16& lo) {
    hi = __float2bfloat16(v);
    lo = __float2bfloat16(v - __bfloat162float(hi));
}
__device__ __forceinline__ float gelu_exact(float v) {
    return 0.5f * v * (1.0f + erff(v * 0.70710678118654752f));
}

// ---------------- embedding ------------------------------------------------
__global__ void k_embed(const int* __restrict__ idx,
                        const float* __restrict__ wte,
                        const float* __restrict__ wpe) {
    int i = blockIdx.x * blockDim.x + threadIdx.x;
    if (i >= BT*Cz) return;
    int c  = i % Cz;
    int bt = i / Cz;
    int t  = bt % Tz;
    int tok = idx[bt];
    g_x[i] = wte[(size_t)tok * Cz + c] + wpe[(size_t)t * Cz + c];
}

// ---------------- weight transpose + bf16 hi/lo split ----------------------
__global__ void k_wprep(const float* __restrict__ W,
                        __nv_bfloat16* __restrict__ Whi,
                        __nv_bfloat16* __restrict__ Wlo, int K, int N) {
    __shared__ float t[32][33];
    int n0 = blockIdx.x * 32, k0 = blockIdx.y * 32;
    int tx = threadIdx.x, ty = threadIdx.y;   // 32 x 8
    #pragma unroll
    for (int j = 0; j < 32; j += 8)
        t[ty + j][tx] = W[(size_t)(k0 + ty + j) * N + n0 + tx];
    __syncthreads();
    #pragma unroll
    for (int j = 0; j < 32; j += 8) {
        float v = t[tx][ty + j];
        __nv_bfloat16 hi, lo; split_bf16(v, hi, lo);
        size_t o = (size_t)(n0 + ty + j) * K + k0 + tx;
        Whi[o] = hi; Wlo[o] = lo;
    }
}

// ---------------- layernorm -> bf16 hi/lo ----------------------------------
__global__ void k_ln(const float* __restrict__ x,
                     const float* __restrict__ w,
                     const float* __restrict__ b,
                     __nv_bfloat16* __restrict__ ohi,
                     __nv_bfloat16* __restrict__ olo) {
    int row = blockIdx.x;
    int tid = threadIdx.x;
    const float* xr = x + (size_t)row * Cz;
    float v0 = xr[tid], v1 = xr[tid + 256], v2 = xr[tid + 512];

    __shared__ float red[256];
    red[tid] = v0 + v1 + v2;
    __syncthreads();
    #pragma unroll
    for (int off = 128; off > 0; off >>= 1) {
        if (tid < off) red[tid] += red[tid + off];
        __syncthreads();
    }
    float mean = red[0] * (1.0f / Cz);
    __syncthreads();
    float d0 = v0 - mean, d1 = v1 - mean, d2 = v2 - mean;
    red[tid] = d0*d0 + d1*d1 + d2*d2;
    __syncthreads();
    #pragma unroll
    for (int off = 128; off > 0; off >>= 1) {
        if (tid < off) red[tid] += red[tid + off];
        __syncthreads();
    }
    float rstd = rsqrtf(red[0] * (1.0f / Cz) + 1e-5f);

    size_t base = (size_t)row * Cz;
    float r0 = d0 * rstd * w[tid]       + b[tid];
    float r1 = d1 * rstd * w[tid + 256] + b[tid + 256];
    float r2 = d2 * rstd * w[tid + 512] + b[tid + 512];
    __nv_bfloat16 hi, lo;
    split_bf16(r0, hi, lo); ohi[base + tid]       = hi; olo[base + tid]       = lo;
    split_bf16(r1, hi, lo); ohi[base + tid + 256] = hi; olo[base + tid + 256] = lo;
    split_bf16(r2, hi, lo); ohi[base + tid + 512] = hi; olo[base + tid + 512] = lo;
}

// ---------------- mma.sync GEMM: BM=64, BN=128, 2 CTAs/SM ------------------
// out[M,N] = (Ahi+Alo)[M,K] @ (Bhi+Blo)[N,K]^T   (3-product bf16 split)
// mode: 0 = +bias->fp32 | 1 = +bias+res->fp32 | 2 = gelu(+bias)->bf16 hi/lo
//       3 = plain->fp32.   8 warps as 2(M)x4(N); warp tile 32x32.
#define MMR 144                        // row stride bytes (128 data + 16 pad)
#define MG_ABYTES (64*MMR)
#define MG_BBYTES (128*MMR)
#define MG_STAGE (2*MG_ABYTES + 2*MG_BBYTES)   // 55296
#define MG_SMEM (2*MG_STAGE)                   // 110592 -> 2 CTAs/SM

__device__ __forceinline__ void mm_load(
    uint32_t so, int chunk, int tid,
    const __nv_bfloat16* Ahi, const __nv_bfloat16* Alo,
    const __nv_bfloat16* Bhi, const __nv_bfloat16* Blo,
    int gm0, int gn0, int K) {
    int k0 = chunk * 64;
    #pragma unroll
    for (int i = tid; i < 3072; i += 256) {
        int r = i >> 3, seg = i & 7;
        const __nv_bfloat16* src;
        uint32_t dst;
        if (r < 64) {
            src = Ahi + (size_t)(gm0 + r) * K;
            dst = so + r * MMR;
        } else if (r < 128) {
            int rr = r - 64;
            src = Alo + (size_t)(gm0 + rr) * K;
            dst = so + MG_ABYTES + rr * MMR;
        } else if (r < 256) {
            int rr = r - 128;
            src = Bhi + (size_t)(gn0 + rr) * K;
            dst = so + 2 * MG_ABYTES + rr * MMR;
        } else {
            int rr = r - 256;
            src = Blo + (size_t)(gn0 + rr) * K;
            dst = so + 2 * MG_ABYTES + MG_BBYTES + rr * MMR;
        }
        cpasync16(dst + seg * 16, src + k0 + seg * 8);
    }
    CP_COMMIT();
}

__global__ void __launch_bounds__(256, 2) k_mgemm(
    const __nv_bfloat16* __restrict__ Ahi, const __nv_bfloat16* __restrict__ Alo,
    const __nv_bfloat16* __restrict__ Bhi, const __nv_bfloat16* __restrict__ Blo,
    const float* __restrict__ bias, const float* res,
    float* outf, __nv_bfloat16* outhi, __nv_bfloat16* outlo,
    int M, int N, int K, int mode) {
    extern __shared__ char smem[];
    uint32_t sbase = smem_u32(smem);
    int tid = threadIdx.x, lane = tid & 31, warp = tid >> 5;
    int wm = (warp >> 2) * 32;           // warp M offset (0/32)
    int wn = (warp & 3) * 32;            // warp N offset (0..96)
    int gn0 = blockIdx.x * 128, gm0 = blockIdx.y * 64;
    int nch = K >> 6;

    float acc[2][4][4];
    #pragma unroll
    for (int i = 0; i < 2; i++)
        #pragma unroll
        for (int j = 0; j < 4; j++)
            #pragma unroll
            for (int e = 0; e < 4; e++) acc[i][j][e] = 0.f;

    mm_load(sbase,            0, tid, Ahi, Alo, Bhi, Blo, gm0, gn0, K);
    mm_load(sbase + MG_STAGE, 1, tid, Ahi, Alo, Bhi, Blo, gm0, gn0, K);

    int lrow = lane & 15;
    int lkb  = (lane >> 4) * 16;         // k-half byte offset

    for (int i = 0; i < nch; i++) {
        if (i + 1 < nch) asm volatile("cp.async.wait_group 1;\n" ::: "memory");
        else             asm volatile("cp.async.wait_group 0;\n" ::: "memory");
        __syncthreads();

        uint32_t so = sbase + (i & 1) * MG_STAGE;
        uint32_t arow = so + (wm + lrow) * MMR;
        uint32_t brow = so + 2 * MG_ABYTES + (wn + lrow) * MMR;

        #pragma unroll
        for (int ks = 0; ks < 4; ks++) {
            uint32_t kb = (uint32_t)(ks * 32) + lkb;
            uint32_t ah[2][4], al[2][4], bh[2][4], bl[2][4];
            #pragma unroll
            for (int mt = 0; mt < 2; mt++) {
                ldm_x4(ah[mt], arow + mt * (16 * MMR) + kb);
                ldm_x4(al[mt], arow + MG_ABYTES + mt * (16 * MMR) + kb);
            }
            #pragma unroll
            for (int np = 0; np < 2; np++) {
                ldm_x4(bh[np], brow + np * (16 * MMR) + kb);
                ldm_x4(bl[np], brow + MG_BBYTES + np * (16 * MMR) + kb);
            }
            #pragma unroll
            for (int mt = 0; mt < 2; mt++) {
                #pragma unroll
                for (int nt = 0; nt < 4; nt++) {
                    int np = nt >> 1, h = nt & 1;
                    mma16816(acc[mt][nt], ah[mt], bh[np][h], bh[np][h + 2]);
                    mma16816(acc[mt][nt], al[mt], bh[np][h], bh[np][h + 2]);
                    mma16816(acc[mt][nt], ah[mt], bl[np][h], bl[np][h + 2]);
                }
            }
        }
        __syncthreads();
        if (i + 2 < nch)
            mm_load(sbase + (i & 1) * MG_STAGE, i + 2, tid,
                    Ahi, Alo, Bhi, Blo, gm0, gn0, K);
    }

    // epilogue
    int r  = lane >> 2;
    int c2 = (lane & 3) * 2;
    #pragma unroll
    for (int mt = 0; mt < 2; mt++) {
        #pragma unroll
        for (int nt = 0; nt < 4; nt++) {
            int m = gm0 + wm + mt * 16 + r;
            int n = gn0 + wn + nt * 8 + c2;
            float* d = acc[mt][nt];
            #pragma unroll
            for (int hh = 0; hh < 2; hh++) {
                int mm = m + hh * 8;
                float v0 = d[2*hh], v1 = d[2*hh + 1];
                if (mode == 2) {
                    v0 = gelu_exact(v0 + bias[n]);
                    v1 = gelu_exact(v1 + bias[n + 1]);
                    __nv_bfloat16 h0, l0, h1, l1;
                    split_bf16(v0, h0, l0); split_bf16(v1, h1, l1);
                    *(__nv_bfloat162*)(outhi + (size_t)mm * N + n) = __nv_bfloat162(h0, h1);
                    *(__nv_bfloat162*)(outlo + (size_t)mm * N + n) = __nv_bfloat162(l0, l1);
                } else {
                    if (mode != 3) { v0 += bias[n]; v1 += bias[n + 1]; }
                    if (mode == 1) {
                        const float2 rv = *(const float2*)(res + (size_t)mm * N + n);
                        v0 += rv.x; v1 += rv.y;
                    }
                    *(float2*)(outf + (size_t)mm * N + n) = make_float2(v0, v1);
                }
            }
        }
    }
}

// ---------------- flash-tiled causal attention -----------------------------
#define ASTR 68                         // floats per smem row (272B, 16B-mult)
#define ASMEM (4 * 64 * ASTR * 4)       // Qs, Ks, Vs, Ps

__global__ void __launch_bounds__(256) k_fattn(
    const float* __restrict__ qkv,
    __nv_bfloat16* __restrict__ yh, __nv_bfloat16* __restrict__ yl) {
    extern __shared__ float sm[];
    float* Qs = sm;
    float* Ks = sm + 64 * ASTR;
    float* Vs = sm + 2 * 64 * ASTR;
    float* Ps = sm + 3 * 64 * ASTR;

    int q0 = blockIdx.x * 64, h = blockIdx.y, b = blockIdx.z;
    int tid = threadIdx.x, lane = tid & 31, warp = tid >> 5;
    int r = lane >> 2, c = lane & 3;
    int qrow = warp * 8 + r;             // local query row
    int qglob = q0 + qrow;

    {
        const float4* g = (const float4*)qkv;
        float4* s4 = (float4*)Qs;
        for (int i = tid; i < 1024; i += 256) {
            int row = i >> 4, sg = i & 15;
            s4[row * 17 + sg] = g[((size_t)(b * Tz + q0 + row) * (3*Cz) + h * 64) / 4 + sg];
        }
    }

    float mrow = -1e30f, lrow = 0.f;
    float oacc[16];
    #pragma unroll
    for (int i = 0; i < 16; i++) oacc[i] = 0.f;

    int ntiles = (q0 >> 6) + 1;
    for (int t = 0; t < ntiles; t++) {
        __syncthreads();
        {
            const float4* g = (const float4*)qkv;
            float4* k4 = (float4*)Ks;
            float4* v4 = (float4*)Vs;
            for (int i = tid; i < 1024; i += 256) {
                int row = i >> 4, sg = i & 15;
                size_t gb = ((size_t)(b * Tz + t * 64 + row) * (3*Cz) + h * 64) / 4 + sg;
                k4[row * 17 + sg] = g[gb + Cz / 4];
                v4[row * 17 + sg] = g[gb + 2 * Cz / 4];
            }
        }
        __syncthreads();

        float s[16];
        #pragma unroll
        for (int kk = 0; kk < 16; kk++) s[kk] = 0.f;
        const float4* q4 = (const float4*)Qs + qrow * 17;
        const float4* k4b = (const float4*)Ks;
        #pragma unroll 4
        for (int d4 = 0; d4 < 16; d4++) {
            float4 qv = q4[d4];
            #pragma unroll
            for (int kk = 0; kk < 16; kk++) {
                float4 kv = k4b[(kk * 4 + c) * 17 + d4];
                s[kk] += qv.x * kv.x + qv.y * kv.y + qv.z * kv.z + qv.w * kv.w;
            }
        }
        bool maskt = (t == ntiles - 1);
        float tmax = -1e30f;
        #pragma unroll
        for (int kk = 0; kk < 16; kk++) {
            s[kk] *= 0.125f;
            if (maskt && (t * 64 + kk * 4 + c) > qglob) s[kk] = -1e30f;
            tmax = fmaxf(tmax, s[kk]);
        }
        tmax = fmaxf(tmax, __shfl_xor_sync(0xffffffffu, tmax, 1));
        tmax = fmaxf(tmax, __shfl_xor_sync(0xffffffffu, tmax, 2));
        float mnew = fmaxf(mrow, tmax);
        float scale = __expf(mrow - mnew);
        float psum = 0.f;
        #pragma unroll
        for (int kk = 0; kk < 16; kk++) {
            float p = __expf(s[kk] - mnew);
            s[kk] = p;
            psum += p;
            Ps[qrow * ASTR + kk * 4 + c] = p;
        }
        psum += __shfl_xor_sync(0xffffffffu, psum, 1);
        psum += __shfl_xor_sync(0xffffffffu, psum, 2);
        lrow = lrow * scale + psum;
        #pragma unroll
        for (int i = 0; i < 16; i++) oacc[i] *= scale;
        mrow = mnew;
        __syncwarp();

        const float4* p4 = (const float4*)Ps + qrow * 17;
        const float4* v4b = (const float4*)Vs;
        #pragma unroll 2
        for (int kq = 0; kq < 16; kq++) {
            float4 pv = p4[kq];
            #pragma unroll
            for (int j = 0; j < 4; j++) {
                float pj = (j == 0) ? pv.x : (j == 1) ? pv.y : (j == 2) ? pv.z : pv.w;
                const float4* vr = v4b + (kq * 4 + j) * 17 + c * 4;
                #pragma unroll
                for (int e = 0; e < 4; e++) {
                    float4 vv = vr[e];
                    oacc[e*4+0] += pj * vv.x;
                    oacc[e*4+1] += pj * vv.y;
                    oacc[e*4+2] += pj * vv.z;
                    oacc[e*4+3] += pj * vv.w;
                }
            }
        }
    }

    float inv = 1.0f / lrow;
    size_t base = (size_t)(b * Tz + qglob) * Cz + h * 64 + c * 16;
    #pragma unroll
    for (int g = 0; g < 8; g++) {
        float v0 = oacc[2*g] * inv, v1 = oacc[2*g+1] * inv;
        __nv_bfloat16 h0, l0, h1, l1;
        split_bf16(v0, h0, l0); split_bf16(v1, h1, l1);
        *(__nv_bfloat162*)(yh + base + 2*g) = __nv_bfloat162(h0, h1);
        *(__nv_bfloat162*)(yl + base + 2*g) = __nv_bfloat162(l0, l1);
    }
}

// ---------------- driver ----------------------------------------------------
extern "C" void kernel_launch(void* const* d_in, const int* in_sizes, int n_in,
                              void* d_out, int out_size) {
    const int*   idx    = (const int*)  d_in[0];
    const float* wte    = (const float*)d_in[1];
    const float* wpe    = (const float*)d_in[2];
    const float* ln1_w  = (const float*)d_in[3];
    const float* ln1_b  = (const float*)d_in[4];
    const float* attn_w = (const float*)d_in[5];
    const float* attn_b = (const float*)d_in[6];
    const float* proj_w = (const float*)d_in[7];
    const float* proj_b = (const float*)d_in[8];
    const float* ln2_w  = (const float*)d_in[9];
    const float* ln2_b  = (const float*)d_in[10];
    const float* fc_w   = (const float*)d_in[11];
    const float* fc_b   = (const float*)d_in[12];
    const float* mlp_w  = (const float*)d_in[13];
    const float* mlp_b  = (const float*)d_in[14];
    const float* lnf_w  = (const float*)d_in[15];
    const float* lnf_b  = (const float*)d_in[16];
    const float* head_w = (const float*)d_in[17];
    float* out = (float*)d_out;

    float *px, *pqkv;
    __nv_bfloat16 *plnh, *plnl, *pyh, *pyl, *phh, *phl;
    __nv_bfloat16 *wqh, *wql, *wph, *wpl, *wfh, *wfl, *wmh, *wml, *whh, *whl;
    cudaGetSymbolAddress((void**)&px,   g_x);
    cudaGetSymbolAddress((void**)&pqkv, g_qkv);
    cudaGetSymbolAddress((void**)&plnh, g_lnh);
    cudaGetSymbolAddress((void**)&plnl, g_lnl);
    cudaGetSymbolAddress((void**)&pyh,  g_yh);
    cudaGetSymbolAddress((void**)&pyl,  g_yl);
    cudaGetSymbolAddress((void**)&phh,  g_hh);
    cudaGetSymbolAddress((void**)&phl,  g_hl);
    cudaGetSymbolAddress((void**)&wqh,  g_wqkv_h);
    cudaGetSymbolAddress((void**)&wql,  g_wqkv_l);
    cudaGetSymbolAddress((void**)&wph,  g_wproj_h);
    cudaGetSymbolAddress((void**)&wpl,  g_wproj_l);
    cudaGetSymbolAddress((void**)&wfh,  g_wfc_h);
    cudaGetSymbolAddress((void**)&wfl,  g_wfc_l);
    cudaGetSymbolAddress((void**)&wmh,  g_wmlp_h);
    cudaGetSymbolAddress((void**)&wml,  g_wmlp_l);
    cudaGetSymbolAddress((void**)&whh,  g_whead_h);
    cudaGetSymbolAddress((void**)&whl,  g_whead_l);

    cudaFuncSetAttribute(k_mgemm, cudaFuncAttributeMaxDynamicSharedMemorySize, MG_SMEM);
    cudaFuncSetAttribute(k_fattn, cudaFuncAttributeMaxDynamicSharedMemorySize, ASMEM);

    dim3 tp(32, 8);
    // ---- my launches 1-3, so that my launch #4 (= ncu capture slot) is
    // the QKV GEMM of layer 0 ----
    k_wprep<<<dim3(3*Cz/32, Cz/32), tp>>>(attn_w, wqh, wql, Cz, 3*Cz);   // 1
    k_embed<<<(BT*Cz + 255) / 256, 256>>>(idx, wte, wpe);                // 2
    k_ln<<<BT, 256>>>(px, ln1_w, ln1_b, plnh, plnl);                     // 3
    // 4: QKV GEMM of layer 0 (ncu capture target)
    k_mgemm<<<dim3(3*Cz/128, BT/64), 256, MG_SMEM>>>(
        plnh, plnl, wqh, wql, attn_b, nullptr, pqkv, nullptr, nullptr,
        BT, 3*Cz, Cz, 0);

    // remaining weight preps
    k_wprep<<<dim3(Cz/32, Cz/32), tp>>>(proj_w, wph, wpl, Cz, Cz);
    k_wprep<<<dim3(4*Cz/32, Cz/32), tp>>>(fc_w, wfh, wfl, Cz, 4*Cz);
    k_wprep<<<dim3(Cz/32, 4*Cz/32), tp>>>(mlp_w, wmh, wml, 4*Cz, Cz);
    for (int l = 1; l < Lz; l++) {
        k_wprep<<<dim3(3*Cz/32, Cz/32), tp>>>(attn_w + (size_t)l*Cz*3*Cz,
            wqh + (size_t)l*3*Cz*Cz, wql + (size_t)l*3*Cz*Cz, Cz, 3*Cz);
        k_wprep<<<dim3(Cz/32, Cz/32), tp>>>(proj_w + (size_t)l*Cz*Cz,
            wph + (size_t)l*Cz*Cz, wpl + (size_t)l*Cz*Cz, Cz, Cz);
        k_wprep<<<dim3(4*Cz/32, Cz/32), tp>>>(fc_w + (size_t)l*Cz*4*Cz,
            wfh + (size_t)l*4*Cz*Cz, wfl + (size_t)l*4*Cz*Cz, Cz, 4*Cz);
        k_wprep<<<dim3(Cz/32, 4*Cz/32), tp>>>(mlp_w + (size_t)l*4*Cz*Cz,
            wmh + (size_t)l*Cz*4*Cz, wml + (size_t)l*Cz*4*Cz, 4*Cz, Cz);
    }
    k_wprep<<<dim3(Vz/32, Cz/32), tp>>>(head_w, whh, whl, Cz, Vz);

    for (int l = 0; l < Lz; l++) {
        const float* ab = attn_b + (size_t)l * 3 * Cz;
        const float* pb = proj_b + (size_t)l * Cz;
        const float* fb = fc_b   + (size_t)l * 4 * Cz;
        const float* mb = mlp_b  + (size_t)l * Cz;

        if (l > 0) {
            k_ln<<<BT, 256>>>(px, ln1_w + (size_t)l*Cz, ln1_b + (size_t)l*Cz, plnh, plnl);
            k_mgemm<<<dim3(3*Cz/128, BT/64), 256, MG_SMEM>>>(
                plnh, plnl, wqh + (size_t)l*3*Cz*Cz, wql + (size_t)l*3*Cz*Cz,
                ab, nullptr, pqkv, nullptr, nullptr, BT, 3*Cz, Cz, 0);
        }
        k_fattn<<<dim3(Tz/64, Hz, Bz), 256, ASMEM>>>(pqkv, pyh, pyl);
        // x += y @ Wproj + b       [4096, 768]
        k_mgemm<<<dim3(Cz/128, BT/64), 256, MG_SMEM>>>(
            pyh, pyl, wph + (size_t)l*Cz*Cz, wpl + (size_t)l*Cz*Cz,
            pb, px, px, nullptr, nullptr, BT, Cz, Cz, 1);
        k_ln<<<BT, 256>>>(px, ln2_w + (size_t)l*Cz, ln2_b + (size_t)l*Cz, plnh, plnl);
        // h = gelu(ln2 @ Wfc + b)  [4096, 3072]
        k_mgemm<<<dim3(4*Cz/128, BT/64), 256, MG_SMEM>>>(
            plnh, plnl, wfh + (size_t)l*4*Cz*Cz, wfl + (size_t)l*4*Cz*Cz,
            fb, nullptr, nullptr, phh, phl, BT, 4*Cz, Cz, 2);
        // x += h @ Wmlp + b        [4096, 768], K=3072
        k_mgemm<<<dim3(Cz/128, BT/64), 256, MG_SMEM>>>(
            phh, phl, wmh + (size_t)l*Cz*4*Cz, wml + (size_t)l*Cz*4*Cz,
            mb, px, px, nullptr, nullptr, BT, Cz, 4*Cz, 1);
    }

    k_ln<<<BT, 256>>>(px, lnf_w, lnf_b, plnh, plnl);
    // logits = lnf @ Whead        [4096, 32000]
    k_mgemm<<<dim3(Vz/128, BT/64), 256, MG_SMEM>>>(
        plnh, plnl, whh, whl, nullptr, nullptr, out, nullptr, nullptr,
        BT, Vz, Cz, 3);
}

// round 8
// speedup vs baseline: 1.0628x; 1.0117x over previous
#include <cuda_runtime.h>
#include <cuda_bf16.h>
#include <math.h>
#include <stdint.h>

#define Bz 4
#define Tz 1024
#define Cz 768
#define Hz 12
#define HDz 64
#define Lz 6
#define Vz 32000
#define BT (Bz*Tz)

// ---------------- scratch (static device globals; no allocations) ----------
__device__ float g_x[BT*Cz];                     // residual stream (fp32)
__device__ __nv_bfloat16 g_lnh[BT*Cz], g_lnl[BT*Cz];     // layernorm out hi/lo
__device__ float g_qkv[BT*3*Cz];                 // qkv (fp32, attention input)
__device__ __nv_bfloat16 g_yh[BT*Cz], g_yl[BT*Cz];       // attention out hi/lo
__device__ __nv_bfloat16 g_hh[BT*4*Cz], g_hl[BT*4*Cz];   // MLP hidden hi/lo
// transposed bf16 hi/lo weights: Wt[N,K] row-major (K contiguous)
__device__ __nv_bfloat16 g_wqkv_h[Lz*3*Cz*Cz], g_wqkv_l[Lz*3*Cz*Cz];
__device__ __nv_bfloat16 g_wproj_h[Lz*Cz*Cz],  g_wproj_l[Lz*Cz*Cz];
__device__ __nv_bfloat16 g_wfc_h[Lz*4*Cz*Cz],  g_wfc_l[Lz*4*Cz*Cz];
__device__ __nv_bfloat16 g_wmlp_h[Lz*Cz*4*Cz], g_wmlp_l[Lz*Cz*4*Cz];
__device__ __nv_bfloat16 g_whead_h[Vz*Cz],     g_whead_l[Vz*Cz];

// ---------------- helpers ---------------------------------------------------
__device__ __forceinline__ uint32_t smem_u32(const void* p) {
    uint32_t a;
    asm("{ .reg .u64 t; cvta.to.shared.u64 t, %1; cvt.u32.u64 %0, t; }"
        : "=r"(a) : "l"(p));
    return a;
}
__device__ __forceinline__ void cpasync16(uint32_t s, const void* g) {
    asm volatile("cp.async.cg.shared.global [%0], [%1], 16;\n" :: "r"(s), "l"(g));
}
#define CP_COMMIT() asm volatile("cp.async.commit_group;\n" ::: "memory")

__device__ __forceinline__ void ldm_x4(uint32_t* r, uint32_t addr) {
    asm volatile("ldmatrix.sync.aligned.m8n8.x4.shared.b16 {%0,%1,%2,%3}, [%4];"
        : "=r"(r[0]), "=r"(r[1]), "=r"(r[2]), "=r"(r[3]) : "r"(addr));
}
__device__ __forceinline__ void mma16816(float* d, const uint32_t* a,
                                         uint32_t b0, uint32_t b1) {
    asm volatile("mma.sync.aligned.m16n8k16.row.col.f32.bf16.bf16.f32 "
        "{%0,%1,%2,%3}, {%4,%5,%6,%7}, {%8,%9}, {%0,%1,%2,%3};"
        : "+f"(d[0]), "+f"(d[1]), "+f"(d[2]), "+f"(d[3])
        : "r"(a[0]), "r"(a[1]), "r"(a[2]), "r"(a[3]), "r"(b0), "r"(b1));
}

__device__ __forceinline__ void split_bf16(float v, __nv_bfloat16& hi, __nv_bfloat16& lo) {
    hi = __float2bfloat16(v);
    lo = __float2bfloat16(v - __bfloat162float(hi));
}
__device__ __forceinline__ float gelu_exact(float v) {
    return 0.5f * v * (1.0f + erff(v * 0.70710678118654752f));
}

// ---------------- embedding ------------------------------------------------
__global__ void k_embed(const int* __restrict__ idx,
                        const float* __restrict__ wte,
                        const float* __restrict__ wpe) {
    int i = blockIdx.x * blockDim.x + threadIdx.x;
    if (i >= BT*Cz) return;
    int c  = i % Cz;
    int bt = i / Cz;
    int t  = bt % Tz;
    int tok = idx[bt];
    g_x[i] = wte[(size_t)tok * Cz + c] + wpe[(size_t)t * Cz + c];
}

// ---------------- weight transpose + bf16 hi/lo split ----------------------
__global__ void k_wprep(const float* __restrict__ W,
                        __nv_bfloat16* __restrict__ Whi,
                        __nv_bfloat16* __restrict__ Wlo, int K, int N) {
    __shared__ float t[32][33];
    int n0 = blockIdx.x * 32, k0 = blockIdx.y * 32;
    int tx = threadIdx.x, ty = threadIdx.y;   // 32 x 8
    #pragma unroll
    for (int j = 0; j < 32; j += 8)
        t[ty + j][tx] = W[(size_t)(k0 + ty + j) * N + n0 + tx];
    __syncthreads();
    #pragma unroll
    for (int j = 0; j < 32; j += 8) {
        float v = t[tx][ty + j];
        __nv_bfloat16 hi, lo; split_bf16(v, hi, lo);
        size_t o = (size_t)(n0 + ty + j) * K + k0 + tx;
        Whi[o] = hi; Wlo[o] = lo;
    }
}

// ---------------- layernorm -> bf16 hi/lo ----------------------------------
__global__ void k_ln(const float* __restrict__ x,
                     const float* __restrict__ w,
                     const float* __restrict__ b,
                     __nv_bfloat16* __restrict__ ohi,
                     __nv_bfloat16* __restrict__ olo) {
    int row = blockIdx.x;
    int tid = threadIdx.x;
    const float* xr = x + (size_t)row * Cz;
    float v0 = xr[tid], v1 = xr[tid + 256], v2 = xr[tid + 512];

    __shared__ float red[256];
    red[tid] = v0 + v1 + v2;
    __syncthreads();
    #pragma unroll
    for (int off = 128; off > 0; off >>= 1) {
        if (tid < off) red[tid] += red[tid + off];
        __syncthreads();
    }
    float mean = red[0] * (1.0f / Cz);
    __syncthreads();
    float d0 = v0 - mean, d1 = v1 - mean, d2 = v2 - mean;
    red[tid] = d0*d0 + d1*d1 + d2*d2;
    __syncthreads();
    #pragma unroll
    for (int off = 128; off > 0; off >>= 1) {
        if (tid < off) red[tid] += red[tid + off];
        __syncthreads();
    }
    float rstd = rsqrtf(red[0] * (1.0f / Cz) + 1e-5f);

    size_t base = (size_t)row * Cz;
    float r0 = d0 * rstd * w[tid]       + b[tid];
    float r1 = d1 * rstd * w[tid + 256] + b[tid + 256];
    float r2 = d2 * rstd * w[tid + 512] + b[tid + 512];
    __nv_bfloat16 hi, lo;
    split_bf16(r0, hi, lo); ohi[base + tid]       = hi; olo[base + tid]       = lo;
    split_bf16(r1, hi, lo); ohi[base + tid + 256] = hi; olo[base + tid + 256] = lo;
    split_bf16(r2, hi, lo); ohi[base + tid + 512] = hi; olo[base + tid + 512] = lo;
}

// ---------------- mma.sync GEMM: BM=64, BN=128, 2 CTAs/SM ------------------
// out[M,N] = (Ahi+Alo)[M,K] @ (Bhi+Blo)[N,K]^T   (3-product bf16 split)
// mode: 0 = +bias->fp32 | 1 = +bias+res->fp32 | 2 = gelu(+bias)->bf16 hi/lo
//       3 = plain->fp32.   8 warps as 2(M)x4(N); warp tile 32x32.
#define MMR 144                        // row stride bytes (128 data + 16 pad)
#define MG_ABYTES (64*MMR)
#define MG_BBYTES (128*MMR)
#define MG_STAGE (2*MG_ABYTES + 2*MG_BBYTES)   // 55296
#define MG_SMEM (2*MG_STAGE)                   // 110592 -> 2 CTAs/SM

__global__ void __launch_bounds__(256, 2) k_mgemm(
    const __nv_bfloat16* __restrict__ Ahi, const __nv_bfloat16* __restrict__ Alo,
    const __nv_bfloat16* __restrict__ Bhi, const __nv_bfloat16* __restrict__ Blo,
    const float* __restrict__ bias, const float* res,
    float* outf, __nv_bfloat16* outhi, __nv_bfloat16* outlo,
    int M, int N, int K, int mode) {
    extern __shared__ char smem[];
    uint32_t sbase = smem_u32(smem);
    int tid = threadIdx.x, lane = tid & 31, warp = tid >> 5;
    int wm = (warp >> 2) * 32;           // warp M offset (0/32)
    int wn = (warp & 3) * 32;            // warp N offset (0..96)
    int gn0 = blockIdx.x * 128, gm0 = blockIdx.y * 64;
    int nch = K >> 6;

    // ---- precomputed load slots: seg fixed, rows r0+32j ----
    int r0 = tid >> 3, seg = tid & 7;
    const __nv_bfloat16* sAh = Ahi + (size_t)(gm0 + r0) * K + seg * 8;
    const __nv_bfloat16* sAl = Alo + (size_t)(gm0 + r0) * K + seg * 8;
    const __nv_bfloat16* sBh = Bhi + (size_t)(gn0 + r0) * K + seg * 8;
    const __nv_bfloat16* sBl = Blo + (size_t)(gn0 + r0) * K + seg * 8;
    uint32_t dsto = (uint32_t)(r0 * MMR + seg * 16);

    auto load_chunk = [&](int stage, int chunk) {
        uint32_t so = sbase + stage * MG_STAGE + dsto;
        size_t ko = (size_t)chunk * 64;
        #pragma unroll
        for (int j = 0; j < 2; j++) {
            cpasync16(so + j * (32 * MMR),              sAh + ko + (size_t)j * 32 * K);
            cpasync16(so + MG_ABYTES + j * (32 * MMR),  sAl + ko + (size_t)j * 32 * K);
        }
        #pragma unroll
        for (int j = 0; j < 4; j++) {
            cpasync16(so + 2 * MG_ABYTES + j * (32 * MMR),
                      sBh + ko + (size_t)j * 32 * K);
            cpasync16(so + 2 * MG_ABYTES + MG_BBYTES + j * (32 * MMR),
                      sBl + ko + (size_t)j * 32 * K);
        }
        CP_COMMIT();
    };

    float acc[2][4][4];
    #pragma unroll
    for (int i = 0; i < 2; i++)
        #pragma unroll
        for (int j = 0; j < 4; j++)
            #pragma unroll
            for (int e = 0; e < 4; e++) acc[i][j][e] = 0.f;

    load_chunk(0, 0);
    load_chunk(1, 1);

    int lrow = lane & 15;
    int lkb  = (lane >> 4) * 16;         // k-half byte offset

    for (int i = 0; i < nch; i++) {
        if (i + 1 < nch) asm volatile("cp.async.wait_group 1;\n" ::: "memory");
        else             asm volatile("cp.async.wait_group 0;\n" ::: "memory");
        __syncthreads();

        uint32_t so = sbase + (i & 1) * MG_STAGE;
        uint32_t arow = so + (wm + lrow) * MMR;
        uint32_t brow = so + 2 * MG_ABYTES + (wn + lrow) * MMR;

        #pragma unroll
        for (int ks = 0; ks < 4; ks++) {
            uint32_t kb = (uint32_t)(ks * 32) + lkb;
            uint32_t ah[2][4], al[2][4], bh[2][4], bl[2][4];
            #pragma unroll
            for (int mt = 0; mt < 2; mt++) {
                ldm_x4(ah[mt], arow + mt * (16 * MMR) + kb);
                ldm_x4(al[mt], arow + MG_ABYTES + mt * (16 * MMR) + kb);
            }
            #pragma unroll
            for (int np = 0; np < 2; np++) {
                ldm_x4(bh[np], brow + np * (16 * MMR) + kb);
                ldm_x4(bl[np], brow + MG_BBYTES + np * (16 * MMR) + kb);
            }
            // product-major: 8 independent MMAs between same-acc touches
            #pragma unroll
            for (int mt = 0; mt < 2; mt++)
                #pragma unroll
                for (int nt = 0; nt < 4; nt++) {
                    int np = nt >> 1, h = nt & 1;
                    mma16816(acc[mt][nt], ah[mt], bh[np][h], bh[np][h + 2]);
                }
            #pragma unroll
            for (int mt = 0; mt < 2; mt++)
                #pragma unroll
                for (int nt = 0; nt < 4; nt++) {
                    int np = nt >> 1, h = nt & 1;
                    mma16816(acc[mt][nt], al[mt], bh[np][h], bh[np][h + 2]);
                }
            #pragma unroll
            for (int mt = 0; mt < 2; mt++)
                #pragma unroll
                for (int nt = 0; nt < 4; nt++) {
                    int np = nt >> 1, h = nt & 1;
                    mma16816(acc[mt][nt], ah[mt], bl[np][h], bl[np][h + 2]);
                }
        }
        __syncthreads();
        if (i + 2 < nch) load_chunk(i & 1, i + 2);
    }

    // epilogue
    int r  = lane >> 2;
    int c2 = (lane & 3) * 2;
    #pragma unroll
    for (int mt = 0; mt < 2; mt++) {
        #pragma unroll
        for (int nt = 0; nt < 4; nt++) {
            int m = gm0 + wm + mt * 16 + r;
            int n = gn0 + wn + nt * 8 + c2;
            float* d = acc[mt][nt];
            #pragma unroll
            for (int hh = 0; hh < 2; hh++) {
                int mm = m + hh * 8;
                float v0 = d[2*hh], v1 = d[2*hh + 1];
                if (mode == 2) {
                    v0 = gelu_exact(v0 + bias[n]);
                    v1 = gelu_exact(v1 + bias[n + 1]);
                    __nv_bfloat16 h0, l0, h1, l1;
                    split_bf16(v0, h0, l0); split_bf16(v1, h1, l1);
                    *(__nv_bfloat162*)(outhi + (size_t)mm * N + n) = __nv_bfloat162(h0, h1);
                    *(__nv_bfloat162*)(outlo + (size_t)mm * N + n) = __nv_bfloat162(l0, l1);
                } else {
                    if (mode != 3) { v0 += bias[n]; v1 += bias[n + 1]; }
                    if (mode == 1) {
                        const float2 rv = *(const float2*)(res + (size_t)mm * N + n);
                        v0 += rv.x; v1 += rv.y;
                    }
                    *(float2*)(outf + (size_t)mm * N + n) = make_float2(v0, v1);
                }
            }
        }
    }
}

// ---------------- flash-tiled causal attention -----------------------------
#define ASTR 68                         // floats per smem row (272B, 16B-mult)
#define ASMEM (4 * 64 * ASTR * 4)       // Qs, Ks, Vs, Ps

__global__ void __launch_bounds__(256) k_fattn(
    const float* __restrict__ qkv,
    __nv_bfloat16* __restrict__ yh, __nv_bfloat16* __restrict__ yl) {
    extern __shared__ float sm[];
    float* Qs = sm;
    float* Ks = sm + 64 * ASTR;
    float* Vs = sm + 2 * 64 * ASTR;
    float* Ps = sm + 3 * 64 * ASTR;

    int q0 = blockIdx.x * 64, h = blockIdx.y, b = blockIdx.z;
    int tid = threadIdx.x, lane = tid & 31, warp = tid >> 5;
    int r = lane >> 2, c = lane & 3;
    int qrow = warp * 8 + r;             // local query row
    int qglob = q0 + qrow;

    {
        const float4* g = (const float4*)qkv;
        float4* s4 = (float4*)Qs;
        for (int i = tid; i < 1024; i += 256) {
            int row = i >> 4, sg = i & 15;
            s4[row * 17 + sg] = g[((size_t)(b * Tz + q0 + row) * (3*Cz) + h * 64) / 4 + sg];
        }
    }

    float mrow = -1e30f, lrow = 0.f;
    float oacc[16];
    #pragma unroll
    for (int i = 0; i < 16; i++) oacc[i] = 0.f;

    int ntiles = (q0 >> 6) + 1;
    for (int t = 0; t < ntiles; t++) {
        __syncthreads();
        {
            const float4* g = (const float4*)qkv;
            float4* k4 = (float4*)Ks;
            float4* v4 = (float4*)Vs;
            for (int i = tid; i < 1024; i += 256) {
                int row = i >> 4, sg = i & 15;
                size_t gb = ((size_t)(b * Tz + t * 64 + row) * (3*Cz) + h * 64) / 4 + sg;
                k4[row * 17 + sg] = g[gb + Cz / 4];
                v4[row * 17 + sg] = g[gb + 2 * Cz / 4];
            }
        }
        __syncthreads();

        float s[16];
        #pragma unroll
        for (int kk = 0; kk < 16; kk++) s[kk] = 0.f;
        const float4* q4 = (const float4*)Qs + qrow * 17;
        const float4* k4b = (const float4*)Ks;
        #pragma unroll 4
        for (int d4 = 0; d4 < 16; d4++) {
            float4 qv = q4[d4];
            #pragma unroll
            for (int kk = 0; kk < 16; kk++) {
                float4 kv = k4b[(kk * 4 + c) * 17 + d4];
                s[kk] += qv.x * kv.x + qv.y * kv.y + qv.z * kv.z + qv.w * kv.w;
            }
        }
        bool maskt = (t == ntiles - 1);
        float tmax = -1e30f;
        #pragma unroll
        for (int kk = 0; kk < 16; kk++) {
            s[kk] *= 0.125f;
            if (maskt && (t * 64 + kk * 4 + c) > qglob) s[kk] = -1e30f;
            tmax = fmaxf(tmax, s[kk]);
        }
        tmax = fmaxf(tmax, __shfl_xor_sync(0xffffffffu, tmax, 1));
        tmax = fmaxf(tmax, __shfl_xor_sync(0xffffffffu, tmax, 2));
        float mnew = fmaxf(mrow, tmax);
        float scale = __expf(mrow - mnew);
        float psum = 0.f;
        #pragma unroll
        for (int kk = 0; kk < 16; kk++) {
            float p = __expf(s[kk] - mnew);
            s[kk] = p;
            psum += p;
            Ps[qrow * ASTR + kk * 4 + c] = p;
        }
        psum += __shfl_xor_sync(0xffffffffu, psum, 1);
        psum += __shfl_xor_sync(0xffffffffu, psum, 2);
        lrow = lrow * scale + psum;
        #pragma unroll
        for (int i = 0; i < 16; i++) oacc[i] *= scale;
        mrow = mnew;
        __syncwarp();

        const float4* p4 = (const float4*)Ps + qrow * 17;
        const float4* v4b = (const float4*)Vs;
        #pragma unroll 2
        for (int kq = 0; kq < 16; kq++) {
            float4 pv = p4[kq];
            #pragma unroll
            for (int j = 0; j < 4; j++) {
                float pj = (j == 0) ? pv.x : (j == 1) ? pv.y : (j == 2) ? pv.z : pv.w;
                const float4* vr = v4b + (kq * 4 + j) * 17 + c * 4;
                #pragma unroll
                for (int e = 0; e < 4; e++) {
                    float4 vv = vr[e];
                    oacc[e*4+0] += pj * vv.x;
                    oacc[e*4+1] += pj * vv.y;
                    oacc[e*4+2] += pj * vv.z;
                    oacc[e*4+3] += pj * vv.w;
                }
            }
        }
    }

    float inv = 1.0f / lrow;
    size_t base = (size_t)(b * Tz + qglob) * Cz + h * 64 + c * 16;
    #pragma unroll
    for (int g = 0; g < 8; g++) {
        float v0 = oacc[2*g] * inv, v1 = oacc[2*g+1] * inv;
        __nv_bfloat16 h0, l0, h1, l1;
        split_bf16(v0, h0, l0); split_bf16(v1, h1, l1);
        *(__nv_bfloat162*)(yh + base + 2*g) = __nv_bfloat162(h0, h1);
        *(__nv_bfloat162*)(yl + base + 2*g) = __nv_bfloat162(l0, l1);
    }
}

// ---------------- driver ----------------------------------------------------
extern "C" void kernel_launch(void* const* d_in, const int* in_sizes, int n_in,
                              void* d_out, int out_size) {
    const int*   idx    = (const int*)  d_in[0];
    const float* wte    = (const float*)d_in[1];
    const float* wpe    = (const float*)d_in[2];
    const float* ln1_w  = (const float*)d_in[3];
    const float* ln1_b  = (const float*)d_in[4];
    const float* attn_w = (const float*)d_in[5];
    const float* attn_b = (const float*)d_in[6];
    const float* proj_w = (const float*)d_in[7];
    const float* proj_b = (const float*)d_in[8];
    const float* ln2_w  = (const float*)d_in[9];
    const float* ln2_b  = (const float*)d_in[10];
    const float* fc_w   = (const float*)d_in[11];
    const float* fc_b   = (const float*)d_in[12];
    const float* mlp_w  = (const float*)d_in[13];
    const float* mlp_b  = (const float*)d_in[14];
    const float* lnf_w  = (const float*)d_in[15];
    const float* lnf_b  = (const float*)d_in[16];
    const float* head_w = (const float*)d_in[17];
    float* out = (float*)d_out;

    float *px, *pqkv;
    __nv_bfloat16 *plnh, *plnl, *pyh, *pyl, *phh, *phl;
    __nv_bfloat16 *wqh, *wql, *wph, *wpl, *wfh, *wfl, *wmh, *wml, *whh, *whl;
    cudaGetSymbolAddress((void**)&px,   g_x);
    cudaGetSymbolAddress((void**)&pqkv, g_qkv);
    cudaGetSymbolAddress((void**)&plnh, g_lnh);
    cudaGetSymbolAddress((void**)&plnl, g_lnl);
    cudaGetSymbolAddress((void**)&pyh,  g_yh);
    cudaGetSymbolAddress((void**)&pyl,  g_yl);
    cudaGetSymbolAddress((void**)&phh,  g_hh);
    cudaGetSymbolAddress((void**)&phl,  g_hl);
    cudaGetSymbolAddress((void**)&wqh,  g_wqkv_h);
    cudaGetSymbolAddress((void**)&wql,  g_wqkv_l);
    cudaGetSymbolAddress((void**)&wph,  g_wproj_h);
    cudaGetSymbolAddress((void**)&wpl,  g_wproj_l);
    cudaGetSymbolAddress((void**)&wfh,  g_wfc_h);
    cudaGetSymbolAddress((void**)&wfl,  g_wfc_l);
    cudaGetSymbolAddress((void**)&wmh,  g_wmlp_h);
    cudaGetSymbolAddress((void**)&wml,  g_wmlp_l);
    cudaGetSymbolAddress((void**)&whh,  g_whead_h);
    cudaGetSymbolAddress((void**)&whl,  g_whead_l);

    cudaFuncSetAttribute(k_mgemm, cudaFuncAttributeMaxDynamicSharedMemorySize, MG_SMEM);
    cudaFuncSetAttribute(k_fattn, cudaFuncAttributeMaxDynamicSharedMemorySize, ASMEM);

    dim3 tp(32, 8);
    // ---- my launches 1-3, so that my launch #4 (= ncu capture slot) is
    // the QKV GEMM of layer 0 ----
    k_wprep<<<dim3(3*Cz/32, Cz/32), tp>>>(attn_w, wqh, wql, Cz, 3*Cz);   // 1
    k_embed<<<(BT*Cz + 255) / 256, 256>>>(idx, wte, wpe);                // 2
    k_ln<<<BT, 256>>>(px, ln1_w, ln1_b, plnh, plnl);                     // 3
    // 4: QKV GEMM of layer 0 (ncu capture target)
    k_mgemm<<<dim3(3*Cz/128, BT/64), 256, MG_SMEM>>>(
        plnh, plnl, wqh, wql, attn_b, nullptr, pqkv, nullptr, nullptr,
        BT, 3*Cz, Cz, 0);

    // remaining weight preps
    k_wprep<<<dim3(Cz/32, Cz/32), tp>>>(proj_w, wph, wpl, Cz, Cz);
    k_wprep<<<dim3(4*Cz/32, Cz/32), tp>>>(fc_w, wfh, wfl, Cz, 4*Cz);
    k_wprep<<<dim3(Cz/32, 4*Cz/32), tp>>>(mlp_w, wmh, wml, 4*Cz, Cz);
    for (int l = 1; l < Lz; l++) {
        k_wprep<<<dim3(3*Cz/32, Cz/32), tp>>>(attn_w + (size_t)l*Cz*3*Cz,
            wqh + (size_t)l*3*Cz*Cz, wql + (size_t)l*3*Cz*Cz, Cz, 3*Cz);
        k_wprep<<<dim3(Cz/32, Cz/32), tp>>>(proj_w + (size_t)l*Cz*Cz,
            wph + (size_t)l*Cz*Cz, wpl + (size_t)l*Cz*Cz, Cz, Cz);
        k_wprep<<<dim3(4*Cz/32, Cz/32), tp>>>(fc_w + (size_t)l*Cz*4*Cz,
            wfh + (size_t)l*4*Cz*Cz, wfl + (size_t)l*4*Cz*Cz, Cz, 4*Cz);
        k_wprep<<<dim3(Cz/32, 4*Cz/32), tp>>>(mlp_w + (size_t)l*4*Cz*Cz,
            wmh + (size_t)l*Cz*4*Cz, wml + (size_t)l*Cz*4*Cz, 4*Cz, Cz);
    }
    k_wprep<<<dim3(Vz/32, Cz/32), tp>>>(head_w, whh, whl, Cz, Vz);

    for (int l = 0; l < Lz; l++) {
        const float* ab = attn_b + (size_t)l * 3 * Cz;
        const float* pb = proj_b + (size_t)l * Cz;
        const float* fb = fc_b   + (size_t)l * 4 * Cz;
        const float* mb = mlp_b  + (size_t)l * Cz;

        if (l > 0) {
            k_ln<<<BT, 256>>>(px, ln1_w + (size_t)l*Cz, ln1_b + (size_t)l*Cz, plnh, plnl);
            k_mgemm<<<dim3(3*Cz/128, BT/64), 256, MG_SMEM>>>(
                plnh, plnl, wqh + (size_t)l*3*Cz*Cz, wql + (size_t)l*3*Cz*Cz,
                ab, nullptr, pqkv, nullptr, nullptr, BT, 3*Cz, Cz, 0);
        }
        k_fattn<<<dim3(Tz/64, Hz, Bz), 256, ASMEM>>>(pqkv, pyh, pyl);
        // x += y @ Wproj + b       [4096, 768]
        k_mgemm<<<dim3(Cz/128, BT/64), 256, MG_SMEM>>>(
            pyh, pyl, wph + (size_t)l*Cz*Cz, wpl + (size_t)l*Cz*Cz,
            pb, px, px, nullptr, nullptr, BT, Cz, Cz, 1);
        k_ln<<<BT, 256>>>(px, ln2_w + (size_t)l*Cz, ln2_b + (size_t)l*Cz, plnh, plnl);
        // h = gelu(ln2 @ Wfc + b)  [4096, 3072]
        k_mgemm<<<dim3(4*Cz/128, BT/64), 256, MG_SMEM>>>(
            plnh, plnl, wfh + (size_t)l*4*Cz*Cz, wfl + (size_t)l*4*Cz*Cz,
            fb, nullptr, nullptr, phh, phl, BT, 4*Cz, Cz, 2);
        // x += h @ Wmlp + b        [4096, 768], K=3072
        k_mgemm<<<dim3(Cz/128, BT/64), 256, MG_SMEM>>>(
            phh, phl, wmh + (size_t)l*Cz*4*Cz, wml + (size_t)l*Cz*4*Cz,
            mb, px, px, nullptr, nullptr, BT, Cz, 4*Cz, 1);
    }

    k_ln<<<BT, 256>>>(px, lnf_w, lnf_b, plnh, plnl);
    // logits = lnf @ Whead        [4096, 32000]
    k_mgemm<<<dim3(Vz/128, BT/64), 256, MG_SMEM>>>(
        plnh, plnl, whh, whl, nullptr, nullptr, out, nullptr, nullptr,
        BT, Vz, Cz, 3);
}